// round 1
// baseline (speedup 1.0000x reference)
#include <cuda_runtime.h>
#include <math.h>
#include <stdint.h>

#define D_MODEL 768
#define HEADS   12
#define GROUPS  2
#define DK      64
#define KVD     128
#define BSZ     4
#define SEQ     2048
#define MTOT    (BSZ*SEQ)

// ---------------- scratch (static device globals: no allocation) ----------------
__device__ float g_qp[(size_t)BSZ*HEADS*SEQ*DK];   // [b][h][s][d]
__device__ float g_kp[(size_t)BSZ*GROUPS*SEQ*DK];  // [b][g][s][d]
__device__ float g_vp[(size_t)BSZ*GROUPS*SEQ*DK];  // [b][g][s][d]
__device__ float g_ao[(size_t)BSZ*SEQ*D_MODEL];    // [b][s][h*64+d]

// ---------------- GEMM: C = A[M,K] @ B[K,N] + bias, 128x128x8 tile, 8x8/thread ---
// MODE 0: plain row-major C[M,N]
// MODE 1: head-split: m -> (b, s), n -> (head, d); C[((b*H+head)*SEQ+s)*64+d], H=N/64
// blockIdx.z selects the (A,B,bias,C) set (lets K and V projections share one launch)
template<int MODE>
__global__ void __launch_bounds__(256) gemm_k(
    const float* __restrict__ A0, const float* __restrict__ B0,
    const float* __restrict__ bias0, float* __restrict__ C0,
    const float* __restrict__ A1, const float* __restrict__ B1,
    const float* __restrict__ bias1, float* __restrict__ C1,
    int N, int K)
{
    const float* A = A0; const float* B = B0; const float* bias = bias0; float* C = C0;
    if (blockIdx.z) { A = A1; B = B1; bias = bias1; C = C1; }

    __shared__ float Ats[8][128];   // [k][m]
    __shared__ float Bs[8][128];    // [k][n]

    const int t    = threadIdx.x;
    const int row0 = blockIdx.y * 128;
    const int n0   = blockIdx.x * 128;
    const int tr   = t >> 4, tc = t & 15;     // thread tile: rows tr*8.., cols tc*8..
    const int ar   = t >> 1, ak = (t & 1) << 2;
    const int bk   = t >> 5, bc = (t & 31) << 2;

    float acc[8][8];
#pragma unroll
    for (int i = 0; i < 8; i++)
#pragma unroll
        for (int j = 0; j < 8; j++) acc[i][j] = 0.f;

    for (int k0 = 0; k0 < K; k0 += 8) {
        float4 av = *(const float4*)(A + (size_t)(row0 + ar) * K + k0 + ak);
        float4 bv = *(const float4*)(B + (size_t)(k0 + bk) * N + n0 + bc);
        __syncthreads();
        Ats[ak + 0][ar] = av.x;
        Ats[ak + 1][ar] = av.y;
        Ats[ak + 2][ar] = av.z;
        Ats[ak + 3][ar] = av.w;
        *(float4*)(&Bs[bk][bc]) = bv;
        __syncthreads();
#pragma unroll
        for (int kk = 0; kk < 8; kk++) {
            float a[8], bb[8];
            *(float4*)(a)     = *(const float4*)(&Ats[kk][tr * 8]);
            *(float4*)(a + 4) = *(const float4*)(&Ats[kk][tr * 8 + 4]);
            *(float4*)(bb)     = *(const float4*)(&Bs[kk][tc * 8]);
            *(float4*)(bb + 4) = *(const float4*)(&Bs[kk][tc * 8 + 4]);
#pragma unroll
            for (int i = 0; i < 8; i++)
#pragma unroll
                for (int j = 0; j < 8; j++) acc[i][j] += a[i] * bb[j];
        }
    }

    // epilogue
#pragma unroll
    for (int i = 0; i < 8; i++) {
        const int m = row0 + tr * 8 + i;
        float o[8];
#pragma unroll
        for (int j = 0; j < 8; j++) o[j] = acc[i][j] + bias[n0 + tc * 8 + j];
        if (MODE == 0) {
            float* dst = C + (size_t)m * N + n0 + tc * 8;
            *(float4*)(dst)     = make_float4(o[0], o[1], o[2], o[3]);
            *(float4*)(dst + 4) = make_float4(o[4], o[5], o[6], o[7]);
        } else {
            const int bi = m >> 11, s = m & 2047;
            const int D0 = n0 + tc * 8;
            const int head = D0 >> 6, d0 = D0 & 63;
            const int H = N >> 6;
            float* dst = C + ((((size_t)(bi * H + head)) * SEQ + s) << 6) + d0;
            *(float4*)(dst)     = make_float4(o[0], o[1], o[2], o[3]);
            *(float4*)(dst + 4) = make_float4(o[4], o[5], o[6], o[7]);
        }
    }
}

// ---------------- Flash attention, fp32, Br=128 q rows / Bc=64 kv rows -----------
// 256 threads. S phase and PV phase: 8 rows x 4 cols per thread (cols interleaved:
// col = tc + 16*jj for bank spread). Online softmax, unscaled scores (faithful).
#define FL_SMEM_FLOATS (128*68 + 64*68 + 64*68 + 128*68 + 3*128)
#define FL_SMEM_BYTES  (FL_SMEM_FLOATS * 4)

__global__ void __launch_bounds__(256, 2) flash_k(
    const float* __restrict__ qp, const float* __restrict__ kp,
    const float* __restrict__ vp, float* __restrict__ ao)
{
    extern __shared__ float sm[];
    float* Qs   = sm;                 // [128][68]
    float* Ks   = Qs + 128 * 68;      // [64][68]
    float* Vs   = Ks + 64 * 68;       // [64][68]
    float* Ss   = Vs + 64 * 68;       // [128][68]
    float* mrow = Ss + 128 * 68;      // [128]
    float* lrow = mrow + 128;         // [128]
    float* crow = lrow + 128;         // [128]

    const int t  = threadIdx.x;
    const int qt = blockIdx.x, h = blockIdx.y, b = blockIdx.z;
    const int g  = h & 1;   // GROUPS=2, tile pattern g0,g1,g0,g1,... -> group = h%2
    const float* qbase = qp + (((size_t)(b * HEADS + h)) * SEQ + (size_t)qt * 128) * DK;
    const float* kbase = kp + (((size_t)(b * GROUPS + g)) * SEQ) * DK;
    const float* vbase = vp + (((size_t)(b * GROUPS + g)) * SEQ) * DK;

    // load Q tile [128][64] row-major (stride 68)
#pragma unroll
    for (int i = 0; i < 8; i++) {
        int f = t + 256 * i;
        int r = f >> 4, d4 = (f & 15) << 2;
        *(float4*)(Qs + r * 68 + d4) = *(const float4*)(qbase + r * 64 + d4);
    }
    if (t < 128) { mrow[t] = -1e30f; lrow[t] = 0.f; }

    const int tr = t >> 4, tc = t & 15;
    float oacc[8][4];
#pragma unroll
    for (int i = 0; i < 8; i++)
#pragma unroll
        for (int jj = 0; jj < 4; jj++) oacc[i][jj] = 0.f;

    for (int kt = 0; kt < SEQ / 64; kt++) {
        __syncthreads();
        // load K,V tile [64][64]
#pragma unroll
        for (int i = 0; i < 4; i++) {
            int f = t + 256 * i;
            int r = f >> 4, d4 = (f & 15) << 2;
            *(float4*)(Ks + r * 68 + d4) = *(const float4*)(kbase + (size_t)(kt * 64 + r) * 64 + d4);
            *(float4*)(Vs + r * 68 + d4) = *(const float4*)(vbase + (size_t)(kt * 64 + r) * 64 + d4);
        }
        __syncthreads();

        // ---- S = Q @ K^T : rows tr*8+i, cols tc + 16*jj
        float sacc[8][4];
#pragma unroll
        for (int i = 0; i < 8; i++)
#pragma unroll
            for (int jj = 0; jj < 4; jj++) sacc[i][jj] = 0.f;
#pragma unroll 4
        for (int d = 0; d < 64; d++) {
            float a[8];
#pragma unroll
            for (int i = 0; i < 8; i++) a[i] = Qs[(tr * 8 + i) * 68 + d];
#pragma unroll
            for (int jj = 0; jj < 4; jj++) {
                float bv = Ks[(tc + 16 * jj) * 68 + d];
#pragma unroll
                for (int i = 0; i < 8; i++) sacc[i][jj] += a[i] * bv;
            }
        }
#pragma unroll
        for (int jj = 0; jj < 4; jj++)
#pragma unroll
            for (int i = 0; i < 8; i++)
                Ss[(tr * 8 + i) * 68 + tc + 16 * jj] = sacc[i][jj];
        __syncthreads();

        // ---- online softmax: 2 threads per row
        {
            const int r = t >> 1, half = t & 1;
            float* srow = Ss + r * 68 + half * 32;
            float mloc = -1e30f;
#pragma unroll 8
            for (int j = 0; j < 32; j++) mloc = fmaxf(mloc, srow[j]);
            mloc = fmaxf(mloc, __shfl_xor_sync(0xffffffffu, mloc, 1));
            const float mold = mrow[r];
            const float mnew = fmaxf(mold, mloc);
            const float corr = __expf(mold - mnew);
            float ssum = 0.f;
#pragma unroll 8
            for (int j = 0; j < 32; j++) {
                float p = __expf(srow[j] - mnew);
                srow[j] = p;
                ssum += p;
            }
            ssum += __shfl_xor_sync(0xffffffffu, ssum, 1);
            if (!half) {
                mrow[r] = mnew;
                lrow[r] = lrow[r] * corr + ssum;
                crow[r] = corr;
            }
        }
        __syncthreads();

        // ---- O = O*corr + P @ V : rows tr*8+i, dims tc + 16*jj
#pragma unroll
        for (int i = 0; i < 8; i++) {
            float cf = crow[tr * 8 + i];
#pragma unroll
            for (int jj = 0; jj < 4; jj++) oacc[i][jj] *= cf;
        }
#pragma unroll 4
        for (int j = 0; j < 64; j++) {
            float a[8];
#pragma unroll
            for (int i = 0; i < 8; i++) a[i] = Ss[(tr * 8 + i) * 68 + j];
#pragma unroll
            for (int jj = 0; jj < 4; jj++) {
                float bv = Vs[j * 68 + tc + 16 * jj];
#pragma unroll
                for (int i = 0; i < 8; i++) oacc[i][jj] += a[i] * bv;
            }
        }
    }

    // ---- write out: ao[b][s][h*64 + d]
#pragma unroll
    for (int i = 0; i < 8; i++) {
        const int r = tr * 8 + i;
        const float linv = 1.f / lrow[r];
        float* dst = ao + ((size_t)(b * SEQ + qt * 128 + r)) * D_MODEL + h * DK;
#pragma unroll
        for (int jj = 0; jj < 4; jj++)
            dst[tc + 16 * jj] = oacc[i][jj] * linv;
    }
}

// ---------------- launch -----------------------------------------------------
extern "C" void kernel_launch(void* const* d_in, const int* in_sizes, int n_in,
                              void* d_out, int out_size)
{
    const float* q  = (const float*)d_in[0];
    const float* k  = (const float*)d_in[1];
    const float* v  = (const float*)d_in[2];
    const float* Wq = (const float*)d_in[3];
    const float* bq = (const float*)d_in[4];
    const float* Wk = (const float*)d_in[5];
    const float* bk = (const float*)d_in[6];
    const float* Wv = (const float*)d_in[7];
    const float* bv = (const float*)d_in[8];
    const float* Wo = (const float*)d_in[9];
    const float* bo = (const float*)d_in[10];
    float* out = (float*)d_out;

    float *qp, *kp, *vp, *ao;
    cudaGetSymbolAddress((void**)&qp, g_qp);
    cudaGetSymbolAddress((void**)&kp, g_kp);
    cudaGetSymbolAddress((void**)&vp, g_vp);
    cudaGetSymbolAddress((void**)&ao, g_ao);

    // 1) Q projection -> head-major qp
    gemm_k<1><<<dim3(D_MODEL / 128, MTOT / 128, 1), 256>>>(
        q, Wq, bq, qp, q, Wq, bq, qp, D_MODEL, D_MODEL);

    // 2) K and V projections in one launch (z selects the operand set)
    gemm_k<1><<<dim3(KVD / 128, MTOT / 128, 2), 256>>>(
        k, Wk, bk, kp, v, Wv, bv, vp, KVD, D_MODEL);

    // 3) flash attention -> ao [b][s][768]
    cudaFuncSetAttribute(flash_k, cudaFuncAttributeMaxDynamicSharedMemorySize, FL_SMEM_BYTES);
    flash_k<<<dim3(SEQ / 128, HEADS, BSZ), 256, FL_SMEM_BYTES>>>(qp, kp, vp, ao);

    // 4) output projection -> d_out
    gemm_k<0><<<dim3(D_MODEL / 128, MTOT / 128, 1), 256>>>(
        ao, Wo, bo, out, ao, Wo, bo, out, D_MODEL, D_MODEL);
}

// round 2
// speedup vs baseline: 1.0935x; 1.0935x over previous
#include <cuda_runtime.h>
#include <math.h>
#include <stdint.h>

#define D_MODEL 768
#define HEADS   12
#define GROUPS  2
#define DK      64
#define KVD     128
#define BSZ     4
#define SEQ     2048
#define MTOT    (BSZ*SEQ)

typedef unsigned long long ull;

// ---------------- packed fp32x2 helpers (Blackwell dual-FP32 pipe) -------------
__device__ __forceinline__ ull pack2(float x, float y) {
    ull r; asm("mov.b64 %0, {%1, %2};" : "=l"(r) : "f"(x), "f"(y)); return r;
}
__device__ __forceinline__ void ffma2(ull& d, ull a, ull b) {
    asm("fma.rn.f32x2 %0, %1, %2, %0;" : "+l"(d) : "l"(a), "l"(b));
}
__device__ __forceinline__ void fmul2(ull& d, ull a) {
    asm("mul.rn.f32x2 %0, %0, %1;" : "+l"(d) : "l"(a));
}
__device__ __forceinline__ float2 u2f(ull v) {
    float2 r; asm("mov.b64 {%0, %1}, %2;" : "=f"(r.x), "=f"(r.y) : "l"(v)); return r;
}

// ---------------- scratch (static device globals: no allocation) ----------------
__device__ float g_qp[(size_t)BSZ*HEADS*SEQ*DK];   // [b][h][s][d]
__device__ float g_kp[(size_t)BSZ*GROUPS*SEQ*DK];  // [b][g][s][d]
__device__ float g_vp[(size_t)BSZ*GROUPS*SEQ*DK];  // [b][g][s][d]
__device__ float g_ao[(size_t)BSZ*SEQ*D_MODEL];    // [b][s][h*64+d]

// ---------------- GEMM: C = A[M,K] @ B[K,N] + bias --------------------------------
// 128x128 tile, K-step 8, double-buffered smem, 8x8 per thread via fp32x2.
// Thread cols: tc*4..tc*4+3  and  64+tc*4..64+tc*4+3 (2-way bank = crossbar min).
// MODE 0: row-major C[M,N].  MODE 1: head-split C[((b*H+head)*SEQ+s)*64+d].
template<int MODE>
__global__ void __launch_bounds__(256, 2) gemm_k(
    const float* __restrict__ A0, const float* __restrict__ B0,
    const float* __restrict__ bias0, float* __restrict__ C0,
    const float* __restrict__ A1, const float* __restrict__ B1,
    const float* __restrict__ bias1, float* __restrict__ C1,
    int N, int K)
{
    const float* A = A0; const float* B = B0; const float* bias = bias0; float* C = C0;
    if (blockIdx.z) { A = A1; B = B1; bias = bias1; C = C1; }

    __shared__ float As[2][8][128];   // [buf][k][m]
    __shared__ float Bs[2][8][128];   // [buf][k][n]

    const int t    = threadIdx.x;
    const int row0 = blockIdx.y * 128;
    const int n0   = blockIdx.x * 128;
    const int tr   = t >> 4, tc = t & 15;
    const int ar   = t >> 1, ak = (t & 1) << 2;   // A loader: row ar, k-offset ak
    const int bk   = t >> 5, bc = (t & 31) << 2;  // B loader

    ull acc[8][4];
#pragma unroll
    for (int i = 0; i < 8; i++)
#pragma unroll
        for (int j = 0; j < 4; j++) acc[i][j] = 0ull;

    // prologue: tile 0
    float4 av = *(const float4*)(A + (size_t)(row0 + ar) * K + ak);
    float4 bv = *(const float4*)(B + (size_t)bk * N + n0 + bc);
    As[0][ak + 0][ar] = av.x; As[0][ak + 1][ar] = av.y;
    As[0][ak + 2][ar] = av.z; As[0][ak + 3][ar] = av.w;
    *(float4*)(&Bs[0][bk][bc]) = bv;
    __syncthreads();

    int buf = 0;
    for (int k0 = 0; k0 < K; k0 += 8) {
        // prefetch next tile into registers
        float4 anx, bnx;
        const bool more = (k0 + 8) < K;
        if (more) {
            anx = *(const float4*)(A + (size_t)(row0 + ar) * K + k0 + 8 + ak);
            bnx = *(const float4*)(B + (size_t)(k0 + 8 + bk) * N + n0 + bc);
        }
        // compute on current buffer
#pragma unroll
        for (int kk = 0; kk < 8; kk++) {
            const float4 a0 = *(const float4*)(&As[buf][kk][tr * 8]);
            const float4 a1 = *(const float4*)(&As[buf][kk][tr * 8 + 4]);
            const ulonglong2 bA = *(const ulonglong2*)(&Bs[buf][kk][tc * 4]);
            const ulonglong2 bB = *(const ulonglong2*)(&Bs[buf][kk][64 + tc * 4]);
            ull a2[8];
            a2[0] = pack2(a0.x, a0.x); a2[1] = pack2(a0.y, a0.y);
            a2[2] = pack2(a0.z, a0.z); a2[3] = pack2(a0.w, a0.w);
            a2[4] = pack2(a1.x, a1.x); a2[5] = pack2(a1.y, a1.y);
            a2[6] = pack2(a1.z, a1.z); a2[7] = pack2(a1.w, a1.w);
#pragma unroll
            for (int i = 0; i < 8; i++) {
                ffma2(acc[i][0], a2[i], bA.x);
                ffma2(acc[i][1], a2[i], bA.y);
                ffma2(acc[i][2], a2[i], bB.x);
                ffma2(acc[i][3], a2[i], bB.y);
            }
        }
        if (more) {
            const int nb = buf ^ 1;
            As[nb][ak + 0][ar] = anx.x; As[nb][ak + 1][ar] = anx.y;
            As[nb][ak + 2][ar] = anx.z; As[nb][ak + 3][ar] = anx.w;
            *(float4*)(&Bs[nb][bk][bc]) = bnx;
        }
        __syncthreads();
        buf ^= 1;
    }

    // epilogue
    const float4 biA = *(const float4*)(bias + n0 + tc * 4);
    const float4 biB = *(const float4*)(bias + n0 + 64 + tc * 4);
#pragma unroll
    for (int i = 0; i < 8; i++) {
        const int m = row0 + tr * 8 + i;
        const float2 p0 = u2f(acc[i][0]), p1 = u2f(acc[i][1]);
        const float2 p2 = u2f(acc[i][2]), p3 = u2f(acc[i][3]);
        float4 oA = make_float4(p0.x + biA.x, p0.y + biA.y, p1.x + biA.z, p1.y + biA.w);
        float4 oB = make_float4(p2.x + biB.x, p2.y + biB.y, p3.x + biB.z, p3.y + biB.w);
        if (MODE == 0) {
            float* dst = C + (size_t)m * N + n0;
            *(float4*)(dst + tc * 4)      = oA;
            *(float4*)(dst + 64 + tc * 4) = oB;
        } else {
            const int bi = m >> 11, s = m & 2047;
            const int H = N >> 6;
            const int headA = n0 >> 6, headB = headA + 1;
            float* dA = C + ((((size_t)(bi * H + headA)) * SEQ + s) << 6) + tc * 4;
            float* dB = C + ((((size_t)(bi * H + headB)) * SEQ + s) << 6) + tc * 4;
            *(float4*)dA = oA;
            *(float4*)dB = oB;
        }
    }
}

// ---------------- Flash attention, fp32x2, Br=128 / Bc=64 ------------------------
// 256 threads, 8 rows x 4 cols per thread.
// S phase: packed over d (both operands adjacent in smem, zero repacks),
//          jj-split into 2 passes to cap live registers.
// PV phase: packed over output dim d (V adjacent), P replicated via ALU-pipe movs.
#define FL_SMEM_FLOATS (128*68 + 64*68 + 64*68 + 128*68 + 3*128)
#define FL_SMEM_BYTES  (FL_SMEM_FLOATS * 4)

__global__ void __launch_bounds__(256, 2) flash_k(
    const float* __restrict__ qp, const float* __restrict__ kp,
    const float* __restrict__ vp, float* __restrict__ ao)
{
    extern __shared__ float sm[];
    float* Qs   = sm;                 // [128][68]
    float* Ks   = Qs + 128 * 68;      // [64][68]
    float* Vs   = Ks + 64 * 68;       // [64][68]
    float* Ss   = Vs + 64 * 68;       // [128][68]
    float* mrow = Ss + 128 * 68;      // [128]
    float* lrow = mrow + 128;         // [128]
    float* crow = lrow + 128;         // [128]

    const int t  = threadIdx.x;
    const int qt = blockIdx.x, h = blockIdx.y, b = blockIdx.z;
    const int g  = h & 1;   // GROUPS=2, tile pattern -> group = h % 2
    const float* qbase = qp + (((size_t)(b * HEADS + h)) * SEQ + (size_t)qt * 128) * DK;
    const float* kbase = kp + (((size_t)(b * GROUPS + g)) * SEQ) * DK;
    const float* vbase = vp + (((size_t)(b * GROUPS + g)) * SEQ) * DK;

    // load Q tile [128][64] (row stride 68)
#pragma unroll
    for (int i = 0; i < 8; i++) {
        int f = t + 256 * i;
        int r = f >> 4, d4 = (f & 15) << 2;
        *(float4*)(Qs + r * 68 + d4) = *(const float4*)(qbase + r * 64 + d4);
    }
    if (t < 128) { mrow[t] = -1e30f; lrow[t] = 0.f; }

    const int tr = t >> 4, tc = t & 15;
    ull oacc[8][2];   // packed over output dims: cols tc*4..tc*4+3
#pragma unroll
    for (int i = 0; i < 8; i++) { oacc[i][0] = 0ull; oacc[i][1] = 0ull; }

    for (int kt = 0; kt < SEQ / 64; kt++) {
        __syncthreads();
        // load K,V tile [64][64]
#pragma unroll
        for (int i = 0; i < 4; i++) {
            int f = t + 256 * i;
            int r = f >> 4, d4 = (f & 15) << 2;
            *(float4*)(Ks + r * 68 + d4) = *(const float4*)(kbase + (size_t)(kt * 64 + r) * 64 + d4);
            *(float4*)(Vs + r * 68 + d4) = *(const float4*)(vbase + (size_t)(kt * 64 + r) * 64 + d4);
        }
        __syncthreads();

        // ---- S = Q @ K^T, packed over d, two jj-passes (cols tc+16*jj)
#pragma unroll
        for (int half = 0; half < 2; half++) {
            const int c0 = tc + 16 * (2 * half);
            const int c1 = tc + 16 * (2 * half + 1);
            ull s2[8][2];
#pragma unroll
            for (int i = 0; i < 8; i++) { s2[i][0] = 0ull; s2[i][1] = 0ull; }
#pragma unroll 4
            for (int d = 0; d < 64; d += 4) {
                const ulonglong2 b0 = *(const ulonglong2*)(Ks + c0 * 68 + d);
                const ulonglong2 b1 = *(const ulonglong2*)(Ks + c1 * 68 + d);
#pragma unroll
                for (int i = 0; i < 8; i++) {
                    const ulonglong2 a = *(const ulonglong2*)(Qs + (tr * 8 + i) * 68 + d);
                    ffma2(s2[i][0], a.x, b0.x);
                    ffma2(s2[i][0], a.y, b0.y);
                    ffma2(s2[i][1], a.x, b1.x);
                    ffma2(s2[i][1], a.y, b1.y);
                }
            }
#pragma unroll
            for (int i = 0; i < 8; i++) {
                const float2 f0 = u2f(s2[i][0]), f1 = u2f(s2[i][1]);
                Ss[(tr * 8 + i) * 68 + c0] = f0.x + f0.y;
                Ss[(tr * 8 + i) * 68 + c1] = f1.x + f1.y;
            }
        }
        __syncthreads();

        // ---- online softmax: 2 threads per row
        {
            const int r = t >> 1, half = t & 1;
            float* srow = Ss + r * 68 + half * 32;
            float mloc = -1e30f;
#pragma unroll 8
            for (int j = 0; j < 32; j++) mloc = fmaxf(mloc, srow[j]);
            mloc = fmaxf(mloc, __shfl_xor_sync(0xffffffffu, mloc, 1));
            const float mold = mrow[r];
            const float mnew = fmaxf(mold, mloc);
            const float corr = __expf(mold - mnew);
            float ssum = 0.f;
#pragma unroll 8
            for (int j = 0; j < 32; j++) {
                float p = __expf(srow[j] - mnew);
                srow[j] = p;
                ssum += p;
            }
            ssum += __shfl_xor_sync(0xffffffffu, ssum, 1);
            if (!half) {
                mrow[r] = mnew;
                lrow[r] = lrow[r] * corr + ssum;
                crow[r] = corr;
            }
        }
        __syncthreads();

        // ---- O = O*corr + P @ V  (packed over output dim; cols tc*4..+3)
#pragma unroll
        for (int i = 0; i < 8; i++) {
            const float cf = crow[tr * 8 + i];
            const ull c2 = pack2(cf, cf);
            fmul2(oacc[i][0], c2);
            fmul2(oacc[i][1], c2);
        }
#pragma unroll 4
        for (int j4 = 0; j4 < 64; j4 += 4) {
            ulonglong2 v0 = *(const ulonglong2*)(Vs + (j4 + 0) * 68 + tc * 4);
            ulonglong2 v1 = *(const ulonglong2*)(Vs + (j4 + 1) * 68 + tc * 4);
            ulonglong2 v2 = *(const ulonglong2*)(Vs + (j4 + 2) * 68 + tc * 4);
            ulonglong2 v3 = *(const ulonglong2*)(Vs + (j4 + 3) * 68 + tc * 4);
#pragma unroll
            for (int i = 0; i < 8; i++) {
                const float4 p = *(const float4*)(Ss + (tr * 8 + i) * 68 + j4);
                const ull p0 = pack2(p.x, p.x), p1 = pack2(p.y, p.y);
                const ull p2 = pack2(p.z, p.z), p3 = pack2(p.w, p.w);
                ffma2(oacc[i][0], p0, v0.x); ffma2(oacc[i][1], p0, v0.y);
                ffma2(oacc[i][0], p1, v1.x); ffma2(oacc[i][1], p1, v1.y);
                ffma2(oacc[i][0], p2, v2.x); ffma2(oacc[i][1], p2, v2.y);
                ffma2(oacc[i][0], p3, v3.x); ffma2(oacc[i][1], p3, v3.y);
            }
        }
    }

    // ---- write out: ao[b][s][h*64 + d], d = tc*4..+3
#pragma unroll
    for (int i = 0; i < 8; i++) {
        const int r = tr * 8 + i;
        const float linv = 1.f / lrow[r];
        const float2 f0 = u2f(oacc[i][0]);
        const float2 f1 = u2f(oacc[i][1]);
        float4 o = make_float4(f0.x * linv, f0.y * linv, f1.x * linv, f1.y * linv);
        float* dst = ao + ((size_t)(b * SEQ + qt * 128 + r)) * D_MODEL + h * DK + tc * 4;
        *(float4*)dst = o;
    }
}

// ---------------- launch -----------------------------------------------------
extern "C" void kernel_launch(void* const* d_in, const int* in_sizes, int n_in,
                              void* d_out, int out_size)
{
    const float* q  = (const float*)d_in[0];
    const float* k  = (const float*)d_in[1];
    const float* v  = (const float*)d_in[2];
    const float* Wq = (const float*)d_in[3];
    const float* bq = (const float*)d_in[4];
    const float* Wk = (const float*)d_in[5];
    const float* bk = (const float*)d_in[6];
    const float* Wv = (const float*)d_in[7];
    const float* bv = (const float*)d_in[8];
    const float* Wo = (const float*)d_in[9];
    const float* bo = (const float*)d_in[10];
    float* out = (float*)d_out;

    float *qp, *kp, *vp, *ao;
    cudaGetSymbolAddress((void**)&qp, g_qp);
    cudaGetSymbolAddress((void**)&kp, g_kp);
    cudaGetSymbolAddress((void**)&vp, g_vp);
    cudaGetSymbolAddress((void**)&ao, g_ao);

    // 1) Q projection -> head-major qp
    gemm_k<1><<<dim3(D_MODEL / 128, MTOT / 128, 1), 256>>>(
        q, Wq, bq, qp, q, Wq, bq, qp, D_MODEL, D_MODEL);

    // 2) K and V projections in one launch (z selects the operand set)
    gemm_k<1><<<dim3(KVD / 128, MTOT / 128, 2), 256>>>(
        k, Wk, bk, kp, v, Wv, bv, vp, KVD, D_MODEL);

    // 3) flash attention -> ao [b][s][768]
    cudaFuncSetAttribute(flash_k, cudaFuncAttributeMaxDynamicSharedMemorySize, FL_SMEM_BYTES);
    flash_k<<<dim3(SEQ / 128, HEADS, BSZ), 256, FL_SMEM_BYTES>>>(qp, kp, vp, ao);

    // 4) output projection -> d_out
    gemm_k<0><<<dim3(D_MODEL / 128, MTOT / 128, 1), 256>>>(
        ao, Wo, bo, out, ao, Wo, bo, out, D_MODEL, D_MODEL);
}